// round 14
// baseline (speedup 1.0000x reference)
#include <cuda_runtime.h>
#include <cuda_bf16.h>
#include <cstdint>
#include <math.h>

#define NT 16384
#define DD 256
#define SHIFT 64.0f
#define LOG2E 1.4426950408889634f
#define EXP_BIAS (-SHIFT * LOG2E)

__device__ float g_row_sum[NT];
__device__ float g_col_sum[NT];
__device__ float g_diag[NT];
__device__ double g_acc;
__device__ __nv_bfloat16 g_Abf[NT * DD];
__device__ __nv_bfloat16 g_Bbf[NT * DD];

__device__ __forceinline__ uint32_t smem_u32(const void* p) {
    uint32_t a;
    asm("{ .reg .u64 t; cvta.to.shared.u64 t, %1; cvt.u32.u64 %0, t; }" : "=r"(a) : "l"(p));
    return a;
}
__device__ __forceinline__ float ex2(float x) {
    float r;
    asm("ex2.approx.f32 %0, %1;" : "=f"(r) : "f"(x));
    return r;
}

// Fused: zero accumulators + fp32 -> bf16 repack + exact fp32 diagonal dot.
__global__ void infonce_prep_diag_kernel(const float* __restrict__ A,
                                         const float* __restrict__ B) {
    int row = (blockIdx.x * blockDim.x + threadIdx.x) >> 5;
    int lane = threadIdx.x & 31;
    if (row >= NT) return;
    if (lane == 1) g_row_sum[row] = 0.0f;
    if (lane == 2) g_col_sum[row] = 0.0f;
    if (row == 0 && lane == 3) g_acc = 0.0;
    const float4* a4 = (const float4*)(A + (size_t)row * DD) + 2 * lane;
    const float4* b4 = (const float4*)(B + (size_t)row * DD) + 2 * lane;
    float4 x0 = a4[0], x1 = a4[1];
    float4 y0 = b4[0], y1 = b4[1];
    uint4 ua, ub;
    ((__nv_bfloat162*)&ua)[0] = __floats2bfloat162_rn(x0.x, x0.y);
    ((__nv_bfloat162*)&ua)[1] = __floats2bfloat162_rn(x0.z, x0.w);
    ((__nv_bfloat162*)&ua)[2] = __floats2bfloat162_rn(x1.x, x1.y);
    ((__nv_bfloat162*)&ua)[3] = __floats2bfloat162_rn(x1.z, x1.w);
    ((__nv_bfloat162*)&ub)[0] = __floats2bfloat162_rn(y0.x, y0.y);
    ((__nv_bfloat162*)&ub)[1] = __floats2bfloat162_rn(y0.z, y0.w);
    ((__nv_bfloat162*)&ub)[2] = __floats2bfloat162_rn(y1.x, y1.y);
    ((__nv_bfloat162*)&ub)[3] = __floats2bfloat162_rn(y1.z, y1.w);
    ((uint4*)(g_Abf + (size_t)row * DD))[lane] = ua;
    ((uint4*)(g_Bbf + (size_t)row * DD))[lane] = ub;
    float s = x0.x * y0.x + x0.y * y0.y + x0.z * y0.z + x0.w * y0.w
            + x1.x * y1.x + x1.y * y1.y + x1.z * y1.z + x1.w * y1.w;
#pragma unroll
    for (int o = 16; o > 0; o >>= 1) s += __shfl_down_sync(0xffffffffu, s, o);
    if (lane == 0) g_diag[row] = s;
}

// Fused bf16 mma.sync GEMM + exp + row/col sum scatter.
// 128x128 CTA tile, 4 warps of 64x64, K staged 64 wide, double buffered.
// Last K-slab: B fragments for all 4 ks held in regs, mt-major MMA with the
// exp epilogue pipelined one 16-row group behind (full within-warp overlap).
__global__ void __launch_bounds__(128, 2) infonce_mma_kernel() {
    extern __shared__ char dynsmem[];
    const uint32_t sb = smem_u32(dynsmem);
    const int tid = threadIdx.x;
    const int wid = tid >> 5, lane = tid & 31;
    const int bi = blockIdx.y, bj = blockIdx.x;
    const int warp_m = wid & 1;
    const int warp_n = wid >> 1;

    const __nv_bfloat16* Abase = g_Abf + (size_t)bi * 128 * DD;
    const __nv_bfloat16* Bbase = g_Bbf + (size_t)bj * 128 * DD;

    float acc[4][8][4];
#pragma unroll
    for (int mt = 0; mt < 4; mt++)
#pragma unroll
        for (int nt = 0; nt < 8; nt++)
#pragma unroll
            for (int r = 0; r < 4; r++) acc[mt][nt][r] = 0.0f;

    const int rl = lane & 7, q = lane >> 3;
    const uint32_t qa_ch = (uint32_t)(q >> 1);
    const uint32_t qb_ch = (uint32_t)(q & 1);
    uint32_t aRel[4], aX7[4];
#pragma unroll
    for (int mt = 0; mt < 4; mt++) {
        int row = warp_m * 64 + mt * 16 + rl + (q & 1) * 8;
        aRel[mt] = (uint32_t)(row * 128);
        aX7[mt] = (uint32_t)(row & 7);
    }
    uint32_t bRel[4], bX7[4];
#pragma unroll
    for (int g = 0; g < 4; g++) {
        int rown = warp_n * 64 + g * 16 + rl + ((q >> 1) & 1) * 8;
        bRel[g] = (uint32_t)(rown * 128);
        bX7[g] = (uint32_t)(rown & 7);
    }

    auto prefetch = [&](int kt, int buf) {
#pragma unroll
        for (int t = 0; t < 16; t++) {
            int id = tid + t * 128;
            int isB = id >> 10;
            int idx = id & 1023;
            int row = idx >> 3, c = idx & 7;
            const __nv_bfloat16* src =
                (isB ? Bbase : Abase) + (size_t)row * DD + kt * 64 + c * 8;
            uint32_t dst = sb + buf * 32768 + isB * 16384 + row * 128 +
                           (((uint32_t)c ^ (uint32_t)(row & 7)) << 4);
            asm volatile("cp.async.cg.shared.global [%0], [%1], 16;"
                         :: "r"(dst), "l"(__cvta_generic_to_global(src)) : "memory");
        }
        asm volatile("cp.async.commit_group;" ::: "memory");
    };

    float csl[8], csh[8];
#pragma unroll
    for (int nt = 0; nt < 8; nt++) { csl[nt] = 0.0f; csh[nt] = 0.0f; }

    prefetch(0, 0);
    int buf = 0;
    // ---- K-slabs 0..2: ks-major mainloop ----
#pragma unroll
    for (int kt = 0; kt < 3; kt++) {
        prefetch(kt + 1, buf ^ 1);
        asm volatile("cp.async.wait_group 1;" ::: "memory");
        __syncthreads();

        const uint32_t bufA = sb + buf * 32768;
        const uint32_t bufB = bufA + 16384;
#pragma unroll
        for (int ks = 0; ks < 4; ks++) {
            uint32_t a[4][4], b[4][4];
#pragma unroll
            for (int mt = 0; mt < 4; mt++) {
                uint32_t addr = bufA + aRel[mt] +
                                ((((uint32_t)(2 * ks) + qa_ch) ^ aX7[mt]) << 4);
                asm volatile("ldmatrix.sync.aligned.m8n8.x4.shared.b16 {%0,%1,%2,%3}, [%4];"
                             : "=r"(a[mt][0]), "=r"(a[mt][1]), "=r"(a[mt][2]), "=r"(a[mt][3])
                             : "r"(addr));
            }
#pragma unroll
            for (int g = 0; g < 4; g++) {
                uint32_t addr = bufB + bRel[g] +
                                ((((uint32_t)(2 * ks) + qb_ch) ^ bX7[g]) << 4);
                asm volatile("ldmatrix.sync.aligned.m8n8.x4.shared.b16 {%0,%1,%2,%3}, [%4];"
                             : "=r"(b[g][0]), "=r"(b[g][1]), "=r"(b[g][2]), "=r"(b[g][3])
                             : "r"(addr));
            }
#pragma unroll
            for (int mt = 0; mt < 4; mt++) {
#pragma unroll
                for (int nt = 0; nt < 8; nt++) {
                    uint32_t b0 = b[nt >> 1][(nt & 1) * 2];
                    uint32_t b1 = b[nt >> 1][(nt & 1) * 2 + 1];
                    asm volatile(
                        "mma.sync.aligned.m16n8k16.row.col.f32.bf16.bf16.f32 "
                        "{%0,%1,%2,%3}, {%4,%5,%6,%7}, {%8,%9}, {%0,%1,%2,%3};"
                        : "+f"(acc[mt][nt][0]), "+f"(acc[mt][nt][1]),
                          "+f"(acc[mt][nt][2]), "+f"(acc[mt][nt][3])
                        : "r"(a[mt][0]), "r"(a[mt][1]), "r"(a[mt][2]), "r"(a[mt][3]),
                          "r"(b0), "r"(b1));
                }
            }
        }
        __syncthreads();
        buf ^= 1;
    }

    // ---- Last K-slab: mt-major, B fragments resident, exp one group behind ----
    asm volatile("cp.async.wait_group 0;" ::: "memory");
    __syncthreads();
    {
        const uint32_t bufA = sb + buf * 32768;
        const uint32_t bufB = bufA + 16384;

        uint32_t bb[4][4][4];   // [ks][g][frag]
#pragma unroll
        for (int ks = 0; ks < 4; ks++)
#pragma unroll
            for (int g = 0; g < 4; g++) {
                uint32_t addr = bufB + bRel[g] +
                                ((((uint32_t)(2 * ks) + qb_ch) ^ bX7[g]) << 4);
                asm volatile("ldmatrix.sync.aligned.m8n8.x4.shared.b16 {%0,%1,%2,%3}, [%4];"
                             : "=r"(bb[ks][g][0]), "=r"(bb[ks][g][1]),
                               "=r"(bb[ks][g][2]), "=r"(bb[ks][g][3])
                             : "r"(addr));
            }

        // exp + row reduction for one completed 16-row group.
        auto exp_group = [&](int m) {
            float rs0 = 0.0f, rs1 = 0.0f;
#pragma unroll
            for (int nt = 0; nt < 8; nt++) {
                float e0 = ex2(fmaf(acc[m][nt][0], LOG2E, EXP_BIAS));
                float e1 = ex2(fmaf(acc[m][nt][1], LOG2E, EXP_BIAS));
                float e2 = ex2(fmaf(acc[m][nt][2], LOG2E, EXP_BIAS));
                float e3 = ex2(fmaf(acc[m][nt][3], LOG2E, EXP_BIAS));
                rs0 += e0 + e1;
                rs1 += e2 + e3;
                csl[nt] += e0 + e2;
                csh[nt] += e1 + e3;
            }
            rs0 += __shfl_xor_sync(0xffffffffu, rs0, 1);
            rs0 += __shfl_xor_sync(0xffffffffu, rs0, 2);
            rs1 += __shfl_xor_sync(0xffffffffu, rs1, 1);
            rs1 += __shfl_xor_sync(0xffffffffu, rs1, 2);
            if ((lane & 3) == 0) {
                int row = bi * 128 + warp_m * 64 + m * 16 + (lane >> 2);
                atomicAdd(&g_row_sum[row], rs0);
                atomicAdd(&g_row_sum[row + 8], rs1);
            }
        };

#pragma unroll
        for (int mt = 0; mt < 4; mt++) {
            uint32_t a[4][4];
#pragma unroll
            for (int ks = 0; ks < 4; ks++) {
                uint32_t addr = bufA + aRel[mt] +
                                ((((uint32_t)(2 * ks) + qa_ch) ^ aX7[mt]) << 4);
                asm volatile("ldmatrix.sync.aligned.m8n8.x4.shared.b16 {%0,%1,%2,%3}, [%4];"
                             : "=r"(a[ks][0]), "=r"(a[ks][1]), "=r"(a[ks][2]), "=r"(a[ks][3])
                             : "r"(addr));
            }
#pragma unroll
            for (int ks = 0; ks < 4; ks++) {
#pragma unroll
                for (int nt = 0; nt < 8; nt++) {
                    uint32_t b0 = bb[ks][nt >> 1][(nt & 1) * 2];
                    uint32_t b1 = bb[ks][nt >> 1][(nt & 1) * 2 + 1];
                    asm volatile(
                        "mma.sync.aligned.m16n8k16.row.col.f32.bf16.bf16.f32 "
                        "{%0,%1,%2,%3}, {%4,%5,%6,%7}, {%8,%9}, {%0,%1,%2,%3};"
                        : "+f"(acc[mt][nt][0]), "+f"(acc[mt][nt][1]),
                          "+f"(acc[mt][nt][2]), "+f"(acc[mt][nt][3])
                        : "r"(a[ks][0]), "r"(a[ks][1]), "r"(a[ks][2]), "r"(a[ks][3]),
                          "r"(b0), "r"(b1));
                }
            }
            // Previous group's exp hides under this group's HMMA chain.
            if (mt > 0) exp_group(mt - 1);
        }
        exp_group(3);
    }

    // ---- column reductions ----
#pragma unroll
    for (int nt = 0; nt < 8; nt++) {
        float cl = csl[nt], ch = csh[nt];
        cl += __shfl_xor_sync(0xffffffffu, cl, 4);
        cl += __shfl_xor_sync(0xffffffffu, cl, 8);
        cl += __shfl_xor_sync(0xffffffffu, cl, 16);
        ch += __shfl_xor_sync(0xffffffffu, ch, 4);
        ch += __shfl_xor_sync(0xffffffffu, ch, 8);
        ch += __shfl_xor_sync(0xffffffffu, ch, 16);
        if (lane < 4) {
            int col = bj * 128 + warp_n * 64 + nt * 8 + 2 * lane;
            atomicAdd(&g_col_sum[col], cl);
            atomicAdd(&g_col_sum[col + 1], ch);
        }
    }
}

// Parallel finalize.
__global__ void infonce_finalize_partial(float*) {
    __shared__ double s[256];
    int tid = threadIdx.x;
    int i = blockIdx.x * 256 + tid;
    double lse_r = (double)logf(g_row_sum[i]) + (double)SHIFT;
    double lse_c = (double)logf(g_col_sum[i]) + (double)SHIFT;
    s[tid] = 0.5 * (lse_r + lse_c) - (double)g_diag[i];
    __syncthreads();
    for (int st = 128; st > 0; st >>= 1) {
        if (tid < st) s[tid] += s[tid + st];
        __syncthreads();
    }
    if (tid == 0) atomicAdd(&g_acc, s[0]);
}

__global__ void infonce_finalize_write(float* out) {
    out[0] = (float)(g_acc / (double)NT);
}

extern "C" void kernel_launch(void* const* d_in, const int* in_sizes, int n_in,
                              void* d_out, int out_size) {
    const float* image_emb = (const float*)d_in[0];
    const float* text_emb  = (const float*)d_in[1];
    float* out = (float*)d_out;

    cudaFuncSetAttribute(infonce_mma_kernel,
                         cudaFuncAttributeMaxDynamicSharedMemorySize, 65536);

    infonce_prep_diag_kernel<<<NT * 32 / 256, 256>>>(image_emb, text_emb);
    infonce_mma_kernel<<<dim3(128, 128), 128, 65536>>>();
    infonce_finalize_partial<<<64, 256>>>(out);
    infonce_finalize_write<<<1, 1>>>(out);
}

// round 16
// speedup vs baseline: 1.1132x; 1.1132x over previous
#include <cuda_runtime.h>
#include <cuda_bf16.h>
#include <cstdint>
#include <math.h>

#define NT 16384
#define DD 256
#define SHIFT 64.0f
#define LOG2E 1.4426950408889634f
#define EXP_BIAS (-SHIFT * LOG2E)

__device__ float g_row_sum[NT];
__device__ float g_col_sum[NT];
__device__ float g_diag[NT];
__device__ double g_acc;
__device__ __nv_bfloat16 g_Abf[NT * DD];
__device__ __nv_bfloat16 g_Bbf[NT * DD];

__device__ __forceinline__ uint32_t smem_u32(const void* p) {
    uint32_t a;
    asm("{ .reg .u64 t; cvta.to.shared.u64 t, %1; cvt.u32.u64 %0, t; }" : "=r"(a) : "l"(p));
    return a;
}
__device__ __forceinline__ float ex2(float x) {
    float r;
    asm("ex2.approx.f32 %0, %1;" : "=f"(r) : "f"(x));
    return r;
}

// Fused: zero accumulators + fp32 -> bf16 repack + exact fp32 diagonal dot.
__global__ void infonce_prep_diag_kernel(const float* __restrict__ A,
                                         const float* __restrict__ B) {
    int row = (blockIdx.x * blockDim.x + threadIdx.x) >> 5;
    int lane = threadIdx.x & 31;
    if (row >= NT) return;
    if (lane == 1) g_row_sum[row] = 0.0f;
    if (lane == 2) g_col_sum[row] = 0.0f;
    if (row == 0 && lane == 3) g_acc = 0.0;
    const float4* a4 = (const float4*)(A + (size_t)row * DD) + 2 * lane;
    const float4* b4 = (const float4*)(B + (size_t)row * DD) + 2 * lane;
    float4 x0 = a4[0], x1 = a4[1];
    float4 y0 = b4[0], y1 = b4[1];
    uint4 ua, ub;
    ((__nv_bfloat162*)&ua)[0] = __floats2bfloat162_rn(x0.x, x0.y);
    ((__nv_bfloat162*)&ua)[1] = __floats2bfloat162_rn(x0.z, x0.w);
    ((__nv_bfloat162*)&ua)[2] = __floats2bfloat162_rn(x1.x, x1.y);
    ((__nv_bfloat162*)&ua)[3] = __floats2bfloat162_rn(x1.z, x1.w);
    ((__nv_bfloat162*)&ub)[0] = __floats2bfloat162_rn(y0.x, y0.y);
    ((__nv_bfloat162*)&ub)[1] = __floats2bfloat162_rn(y0.z, y0.w);
    ((__nv_bfloat162*)&ub)[2] = __floats2bfloat162_rn(y1.x, y1.y);
    ((__nv_bfloat162*)&ub)[3] = __floats2bfloat162_rn(y1.z, y1.w);
    ((uint4*)(g_Abf + (size_t)row * DD))[lane] = ua;
    ((uint4*)(g_Bbf + (size_t)row * DD))[lane] = ub;
    float s = x0.x * y0.x + x0.y * y0.y + x0.z * y0.z + x0.w * y0.w
            + x1.x * y1.x + x1.y * y1.y + x1.z * y1.z + x1.w * y1.w;
#pragma unroll
    for (int o = 16; o > 0; o >>= 1) s += __shfl_down_sync(0xffffffffu, s, o);
    if (lane == 0) g_diag[row] = s;
}

// Fused bf16 mma.sync GEMM + exp + row/col sum scatter.
// 128x128 CTA tile, 4 warps of 64x64, K staged 64 wide, THREE 32KB stages
// (96KB smem, 2 CTAs/SM). One __syncthreads per slab. Final ks of the last
// slab interleaves per-16-row-group EX2 with the next group's HMMA chain.
__global__ void __launch_bounds__(128, 2) infonce_mma_kernel() {
    extern __shared__ char dynsmem[];
    const uint32_t sb = smem_u32(dynsmem);
    const int tid = threadIdx.x;
    const int wid = tid >> 5, lane = tid & 31;
    const int bi = blockIdx.y, bj = blockIdx.x;
    const int warp_m = wid & 1;
    const int warp_n = wid >> 1;

    const __nv_bfloat16* Abase = g_Abf + (size_t)bi * 128 * DD;
    const __nv_bfloat16* Bbase = g_Bbf + (size_t)bj * 128 * DD;

    float acc[4][8][4];
#pragma unroll
    for (int mt = 0; mt < 4; mt++)
#pragma unroll
        for (int nt = 0; nt < 8; nt++)
#pragma unroll
            for (int r = 0; r < 4; r++) acc[mt][nt][r] = 0.0f;

    const int rl = lane & 7, q = lane >> 3;
    const uint32_t qa_ch = (uint32_t)(q >> 1);
    const uint32_t qb_ch = (uint32_t)(q & 1);
    uint32_t aRel[4], aX7[4];
#pragma unroll
    for (int mt = 0; mt < 4; mt++) {
        int row = warp_m * 64 + mt * 16 + rl + (q & 1) * 8;
        aRel[mt] = (uint32_t)(row * 128);
        aX7[mt] = (uint32_t)(row & 7);
    }
    uint32_t bRel[4], bX7[4];
#pragma unroll
    for (int g = 0; g < 4; g++) {
        int rown = warp_n * 64 + g * 16 + rl + ((q >> 1) & 1) * 8;
        bRel[g] = (uint32_t)(rown * 128);
        bX7[g] = (uint32_t)(rown & 7);
    }

    auto prefetch = [&](int kt, int stage) {
#pragma unroll
        for (int t = 0; t < 16; t++) {
            int id = tid + t * 128;
            int isB = id >> 10;
            int idx = id & 1023;
            int row = idx >> 3, c = idx & 7;
            const __nv_bfloat16* src =
                (isB ? Bbase : Abase) + (size_t)row * DD + kt * 64 + c * 8;
            uint32_t dst = sb + stage * 32768 + isB * 16384 + row * 128 +
                           (((uint32_t)c ^ (uint32_t)(row & 7)) << 4);
            asm volatile("cp.async.cg.shared.global [%0], [%1], 16;"
                         :: "r"(dst), "l"(__cvta_generic_to_global(src)) : "memory");
        }
        asm volatile("cp.async.commit_group;" ::: "memory");
    };

    float rs[4][2];
#pragma unroll
    for (int mt = 0; mt < 4; mt++) { rs[mt][0] = 0.0f; rs[mt][1] = 0.0f; }
    float csl[8], csh[8];
#pragma unroll
    for (int nt = 0; nt < 8; nt++) { csl[nt] = 0.0f; csh[nt] = 0.0f; }

    // Plain slab compute (no epilogue), ks-major.
    auto compute_slab = [&](int stage) {
        const uint32_t bufA = sb + stage * 32768;
        const uint32_t bufB = bufA + 16384;
#pragma unroll
        for (int ks = 0; ks < 4; ks++) {
            uint32_t a[4][4], b[4][4];
#pragma unroll
            for (int mt = 0; mt < 4; mt++) {
                uint32_t addr = bufA + aRel[mt] +
                                ((((uint32_t)(2 * ks) + qa_ch) ^ aX7[mt]) << 4);
                asm volatile("ldmatrix.sync.aligned.m8n8.x4.shared.b16 {%0,%1,%2,%3}, [%4];"
                             : "=r"(a[mt][0]), "=r"(a[mt][1]), "=r"(a[mt][2]), "=r"(a[mt][3])
                             : "r"(addr));
            }
#pragma unroll
            for (int g = 0; g < 4; g++) {
                uint32_t addr = bufB + bRel[g] +
                                ((((uint32_t)(2 * ks) + qb_ch) ^ bX7[g]) << 4);
                asm volatile("ldmatrix.sync.aligned.m8n8.x4.shared.b16 {%0,%1,%2,%3}, [%4];"
                             : "=r"(b[g][0]), "=r"(b[g][1]), "=r"(b[g][2]), "=r"(b[g][3])
                             : "r"(addr));
            }
#pragma unroll
            for (int mt = 0; mt < 4; mt++) {
#pragma unroll
                for (int nt = 0; nt < 8; nt++) {
                    uint32_t b0 = b[nt >> 1][(nt & 1) * 2];
                    uint32_t b1 = b[nt >> 1][(nt & 1) * 2 + 1];
                    asm volatile(
                        "mma.sync.aligned.m16n8k16.row.col.f32.bf16.bf16.f32 "
                        "{%0,%1,%2,%3}, {%4,%5,%6,%7}, {%8,%9}, {%0,%1,%2,%3};"
                        : "+f"(acc[mt][nt][0]), "+f"(acc[mt][nt][1]),
                          "+f"(acc[mt][nt][2]), "+f"(acc[mt][nt][3])
                        : "r"(a[mt][0]), "r"(a[mt][1]), "r"(a[mt][2]), "r"(a[mt][3]),
                          "r"(b0), "r"(b1));
                }
            }
        }
    };

    // Issue slabs 0,1,2 into stages 0,1,2.
    prefetch(0, 0);
    prefetch(1, 1);
    prefetch(2, 2);

    // iter 0: slab0
    asm volatile("cp.async.wait_group 2;" ::: "memory");
    __syncthreads();
    compute_slab(0);

    // iter 1: slab1 (+ issue slab3 into stage0 — all reads of stage0 done)
    asm volatile("cp.async.wait_group 1;" ::: "memory");
    __syncthreads();
    prefetch(3, 0);
    compute_slab(1);

    // iter 2: slab2
    asm volatile("cp.async.wait_group 1;" ::: "memory");
    __syncthreads();
    compute_slab(2);

    // iter 3: slab3 with fused exp on the final ks (R12 pattern)
    asm volatile("cp.async.wait_group 0;" ::: "memory");
    __syncthreads();
    {
        const uint32_t bufA = sb;            // stage 0
        const uint32_t bufB = sb + 16384;
#pragma unroll
        for (int ks = 0; ks < 4; ks++) {
            uint32_t a[4][4], b[4][4];
#pragma unroll
            for (int mt = 0; mt < 4; mt++) {
                uint32_t addr = bufA + aRel[mt] +
                                ((((uint32_t)(2 * ks) + qa_ch) ^ aX7[mt]) << 4);
                asm volatile("ldmatrix.sync.aligned.m8n8.x4.shared.b16 {%0,%1,%2,%3}, [%4];"
                             : "=r"(a[mt][0]), "=r"(a[mt][1]), "=r"(a[mt][2]), "=r"(a[mt][3])
                             : "r"(addr));
            }
#pragma unroll
            for (int g = 0; g < 4; g++) {
                uint32_t addr = bufB + bRel[g] +
                                ((((uint32_t)(2 * ks) + qb_ch) ^ bX7[g]) << 4);
                asm volatile("ldmatrix.sync.aligned.m8n8.x4.shared.b16 {%0,%1,%2,%3}, [%4];"
                             : "=r"(b[g][0]), "=r"(b[g][1]), "=r"(b[g][2]), "=r"(b[g][3])
                             : "r"(addr));
            }
            const bool last = (ks == 3);
#pragma unroll
            for (int mt = 0; mt < 4; mt++) {
#pragma unroll
                for (int nt = 0; nt < 8; nt++) {
                    uint32_t b0 = b[nt >> 1][(nt & 1) * 2];
                    uint32_t b1 = b[nt >> 1][(nt & 1) * 2 + 1];
                    asm volatile(
                        "mma.sync.aligned.m16n8k16.row.col.f32.bf16.bf16.f32 "
                        "{%0,%1,%2,%3}, {%4,%5,%6,%7}, {%8,%9}, {%0,%1,%2,%3};"
                        : "+f"(acc[mt][nt][0]), "+f"(acc[mt][nt][1]),
                          "+f"(acc[mt][nt][2]), "+f"(acc[mt][nt][3])
                        : "r"(a[mt][0]), "r"(a[mt][1]), "r"(a[mt][2]), "r"(a[mt][3]),
                          "r"(b0), "r"(b1));
                }
                if (last) {
                    float rs0 = 0.0f, rs1 = 0.0f;
#pragma unroll
                    for (int nt = 0; nt < 8; nt++) {
                        float e0 = ex2(fmaf(acc[mt][nt][0], LOG2E, EXP_BIAS));
                        float e1 = ex2(fmaf(acc[mt][nt][1], LOG2E, EXP_BIAS));
                        float e2 = ex2(fmaf(acc[mt][nt][2], LOG2E, EXP_BIAS));
                        float e3 = ex2(fmaf(acc[mt][nt][3], LOG2E, EXP_BIAS));
                        rs0 += e0 + e1;
                        rs1 += e2 + e3;
                        csl[nt] += e0 + e2;
                        csh[nt] += e1 + e3;
                    }
                    rs[mt][0] = rs0;
                    rs[mt][1] = rs1;
                }
            }
        }
    }

    // ---- deferred reductions (shuffles + atomics only) ----
#pragma unroll
    for (int mt = 0; mt < 4; mt++) {
        float rs0 = rs[mt][0], rs1 = rs[mt][1];
        rs0 += __shfl_xor_sync(0xffffffffu, rs0, 1);
        rs0 += __shfl_xor_sync(0xffffffffu, rs0, 2);
        rs1 += __shfl_xor_sync(0xffffffffu, rs1, 1);
        rs1 += __shfl_xor_sync(0xffffffffu, rs1, 2);
        if ((lane & 3) == 0) {
            int row = bi * 128 + warp_m * 64 + mt * 16 + (lane >> 2);
            atomicAdd(&g_row_sum[row], rs0);
            atomicAdd(&g_row_sum[row + 8], rs1);
        }
    }
#pragma unroll
    for (int nt = 0; nt < 8; nt++) {
        float cl = csl[nt], ch = csh[nt];
        cl += __shfl_xor_sync(0xffffffffu, cl, 4);
        cl += __shfl_xor_sync(0xffffffffu, cl, 8);
        cl += __shfl_xor_sync(0xffffffffu, cl, 16);
        ch += __shfl_xor_sync(0xffffffffu, ch, 4);
        ch += __shfl_xor_sync(0xffffffffu, ch, 8);
        ch += __shfl_xor_sync(0xffffffffu, ch, 16);
        if (lane < 4) {
            int col = bj * 128 + warp_n * 64 + nt * 8 + 2 * lane;
            atomicAdd(&g_col_sum[col], cl);
            atomicAdd(&g_col_sum[col + 1], ch);
        }
    }
}

// Parallel finalize.
__global__ void infonce_finalize_partial(float*) {
    __shared__ double s[256];
    int tid = threadIdx.x;
    int i = blockIdx.x * 256 + tid;
    double lse_r = (double)logf(g_row_sum[i]) + (double)SHIFT;
    double lse_c = (double)logf(g_col_sum[i]) + (double)SHIFT;
    s[tid] = 0.5 * (lse_r + lse_c) - (double)g_diag[i];
    __syncthreads();
    for (int st = 128; st > 0; st >>= 1) {
        if (tid < st) s[tid] += s[tid + st];
        __syncthreads();
    }
    if (tid == 0) atomicAdd(&g_acc, s[0]);
}

__global__ void infonce_finalize_write(float* out) {
    out[0] = (float)(g_acc / (double)NT);
}

extern "C" void kernel_launch(void* const* d_in, const int* in_sizes, int n_in,
                              void* d_out, int out_size) {
    const float* image_emb = (const float*)d_in[0];
    const float* text_emb  = (const float*)d_in[1];
    float* out = (float*)d_out;

    cudaFuncSetAttribute(infonce_mma_kernel,
                         cudaFuncAttributeMaxDynamicSharedMemorySize, 98304);

    infonce_prep_diag_kernel<<<NT * 32 / 256, 256>>>(image_emb, text_emb);
    infonce_mma_kernel<<<dim3(128, 128), 128, 98304>>>();
    infonce_finalize_partial<<<64, 256>>>(out);
    infonce_finalize_write<<<1, 1>>>(out);
}